// round 2
// baseline (speedup 1.0000x reference)
#include <cuda_runtime.h>
#include <cuda_fp16.h>
#include <math.h>
#include <stdint.h>

#define TOKENS 4096
#define DM     1024
#define DFF    4096
#define NE     8

// ---- static device scratch (no allocation in kernel_launch) ----
static __device__ __half g_h[(size_t)NE * TOKENS * DFF];   // 256 MB gelu intermediate
static __device__ int    g_tok[NE * TOKENS];
static __device__ float  g_gate[NE * TOKENS];
static __device__ int    g_cnt[NE];

__global__ void zero_cnt_kernel() {
    if (threadIdx.x < NE) g_cnt[threadIdx.x] = 0;
}

// ---------------- gating: logits -> top-2 -> softmax -> routing lists ----------------
__global__ void gate_kernel(const float* __restrict__ x,
                            const float* __restrict__ Wg,
                            const float* __restrict__ bg) {
    __shared__ float sWg[DM * NE];   // 32 KB
    const int tid = threadIdx.x;
    for (int i = tid; i < DM * NE; i += 256) sWg[i] = Wg[i];
    __syncthreads();

    const int warp = tid >> 5, lane = tid & 31;
    const int t = blockIdx.x * 8 + warp;
    const float* xr = x + (size_t)t * DM;

    float acc[NE];
#pragma unroll
    for (int e = 0; e < NE; e++) acc[e] = 0.f;
    for (int i = 0; i < DM / 32; i++) {
        const int r = i * 32 + lane;
        const float xv = xr[r];
#pragma unroll
        for (int e = 0; e < NE; e++) acc[e] += xv * sWg[r * NE + e];
    }
#pragma unroll
    for (int e = 0; e < NE; e++)
#pragma unroll
        for (int off = 16; off > 0; off >>= 1)
            acc[e] += __shfl_xor_sync(0xFFFFFFFFu, acc[e], off);

    if (lane == 0) {
        float v[NE];
#pragma unroll
        for (int e = 0; e < NE; e++) v[e] = acc[e] + bg[e];
        // top-1 (strict > keeps lowest index on tie, matching jax top_k)
        int b0 = 0; float m0v = v[0];
#pragma unroll
        for (int e = 1; e < NE; e++) if (v[e] > m0v) { m0v = v[e]; b0 = e; }
        // top-2
        int b1i = (b0 == 0) ? 1 : 0; float m1v = v[(b0 == 0) ? 1 : 0];
#pragma unroll
        for (int e = 0; e < NE; e++)
            if (e != b0 && v[e] > m1v) { m1v = v[e]; b1i = e; }

        const float e1 = expf(m1v - m0v);
        const float s  = 1.f + e1;
        const float gA = 1.f / s;     // gate for b0 (the max)
        const float gB = e1 / s;      // gate for b1i

        int p = atomicAdd(&g_cnt[b0], 1);
        g_tok[b0 * TOKENS + p] = t; g_gate[b0 * TOKENS + p] = gA;
        p = atomicAdd(&g_cnt[b1i], 1);
        g_tok[b1i * TOKENS + p] = t; g_gate[b1i * TOKENS + p] = gB;
    }
}

// ---------------- grouped GEMM1: h = gelu(x[tok] @ W1[e] + b1[e]), fp16 out ----------------
__global__ void __launch_bounds__(256, 2)
gemm1_kernel(const float* __restrict__ x,
             const float* __restrict__ W1,
             const float* __restrict__ b1) {
    const int e  = blockIdx.y;
    const int c  = g_cnt[e];
    const int m0 = blockIdx.z * 128;
    if (m0 >= c) return;
    const int n0 = blockIdx.x * 128;

    __shared__ float As[2][16][128];
    __shared__ float Bs[2][16][128];

    const int tid   = threadIdx.x;
    const int arow  = tid >> 1, akoff = (tid & 1) * 8;
    const bool avalid = (m0 + arow) < c;
    const float* xrow =
        x + (size_t)(avalid ? g_tok[e * TOKENS + m0 + arow] : 0) * DM;

    const int bk = tid >> 4, bn = (tid & 15) * 8;
    const float* wb = W1 + (size_t)e * DM * DFF + n0 + bn;

    const int ty = tid >> 4, tx = tid & 15;

    float acc[8][8];
#pragma unroll
    for (int i = 0; i < 8; i++)
#pragma unroll
        for (int j = 0; j < 8; j++) acc[i][j] = 0.f;

    float ar[8], br[8];

    auto loadg = [&](int kt) {
        if (avalid) {
            float4 a0 = *(const float4*)(xrow + kt * 16 + akoff);
            float4 a1 = *(const float4*)(xrow + kt * 16 + akoff + 4);
            ar[0]=a0.x; ar[1]=a0.y; ar[2]=a0.z; ar[3]=a0.w;
            ar[4]=a1.x; ar[5]=a1.y; ar[6]=a1.z; ar[7]=a1.w;
        } else {
#pragma unroll
            for (int j = 0; j < 8; j++) ar[j] = 0.f;
        }
        const float* wr = wb + (size_t)(kt * 16 + bk) * DFF;
        float4 b0 = *(const float4*)(wr);
        float4 b1v = *(const float4*)(wr + 4);
        br[0]=b0.x; br[1]=b0.y; br[2]=b0.z; br[3]=b0.w;
        br[4]=b1v.x; br[5]=b1v.y; br[6]=b1v.z; br[7]=b1v.w;
    };
    auto store_s = [&](int buf) {
#pragma unroll
        for (int j = 0; j < 8; j++) As[buf][akoff + j][arow] = ar[j];
        *(float4*)&Bs[buf][bk][bn]     = make_float4(br[0], br[1], br[2], br[3]);
        *(float4*)&Bs[buf][bk][bn + 4] = make_float4(br[4], br[5], br[6], br[7]);
    };

    const int NK = DM / 16;
    loadg(0); store_s(0); __syncthreads();
    for (int kt = 0; kt < NK; kt++) {
        const int cur = kt & 1;
        if (kt + 1 < NK) loadg(kt + 1);
#pragma unroll
        for (int k = 0; k < 16; k++) {
            float4 a0 = *(const float4*)&As[cur][k][ty * 8];
            float4 a1 = *(const float4*)&As[cur][k][ty * 8 + 4];
            float4 b0 = *(const float4*)&Bs[cur][k][tx * 8];
            float4 b1v = *(const float4*)&Bs[cur][k][tx * 8 + 4];
            float av[8] = {a0.x,a0.y,a0.z,a0.w,a1.x,a1.y,a1.z,a1.w};
            float bv[8] = {b0.x,b0.y,b0.z,b0.w,b1v.x,b1v.y,b1v.z,b1v.w};
#pragma unroll
            for (int i = 0; i < 8; i++)
#pragma unroll
                for (int j = 0; j < 8; j++)
                    acc[i][j] = fmaf(av[i], bv[j], acc[i][j]);
        }
        if (kt + 1 < NK) store_s(cur ^ 1);
        __syncthreads();
    }

    // epilogue: bias + gelu(tanh) -> fp16 h
    const float* b1e = b1 + (size_t)e * DFF + n0 + tx * 8;
#pragma unroll
    for (int i = 0; i < 8; i++) {
        const int r = ty * 8 + i;
        if (m0 + r < c) {
            __half hv[8];
#pragma unroll
            for (int j = 0; j < 8; j++) {
                const float vv = acc[i][j] + b1e[j];
                const float v3 = vv * vv * vv;
                const float g = 0.5f * vv *
                    (1.f + tanhf(0.7978845608028654f * (vv + 0.044715f * v3)));
                hv[j] = __float2half_rn(g);
            }
            __half* hp = g_h + ((size_t)(e * TOKENS + m0 + r)) * DFF + n0 + tx * 8;
            *(uint4*)hp = *(uint4*)hv;
        }
    }
}

// ---------------- grouped GEMM2: out[t] += gate * (h @ W2[e] + b2[e]) ----------------
__global__ void __launch_bounds__(256, 2)
gemm2_kernel(const float* __restrict__ W2,
             const float* __restrict__ b2,
             float* __restrict__ out) {
    const int e  = blockIdx.y;
    const int c  = g_cnt[e];
    const int m0 = blockIdx.z * 128;
    if (m0 >= c) return;
    const int n0 = blockIdx.x * 128;

    __shared__ float As[2][16][128];
    __shared__ float Bs[2][16][128];

    const int tid   = threadIdx.x;
    const int arow  = tid >> 1, akoff = (tid & 1) * 8;
    const bool avalid = (m0 + arow) < c;
    const __half* hrow =
        g_h + (size_t)(e * TOKENS + m0 + (avalid ? arow : 0)) * DFF;

    const int bk = tid >> 4, bn = (tid & 15) * 8;
    const float* wb = W2 + (size_t)e * DFF * DM + n0 + bn;

    const int ty = tid >> 4, tx = tid & 15;

    float acc[8][8];
#pragma unroll
    for (int i = 0; i < 8; i++)
#pragma unroll
        for (int j = 0; j < 8; j++) acc[i][j] = 0.f;

    float ar[8], br[8];

    auto loadg = [&](int kt) {
        if (avalid) {
            uint4 hv = *(const uint4*)(hrow + kt * 16 + akoff);
            const __half2* hp = (const __half2*)&hv;
#pragma unroll
            for (int p = 0; p < 4; p++) {
                float2 f = __half22float2(hp[p]);
                ar[2 * p] = f.x; ar[2 * p + 1] = f.y;
            }
        } else {
#pragma unroll
            for (int j = 0; j < 8; j++) ar[j] = 0.f;
        }
        const float* wr = wb + (size_t)(kt * 16 + bk) * DM;
        float4 b0 = *(const float4*)(wr);
        float4 b1v = *(const float4*)(wr + 4);
        br[0]=b0.x; br[1]=b0.y; br[2]=b0.z; br[3]=b0.w;
        br[4]=b1v.x; br[5]=b1v.y; br[6]=b1v.z; br[7]=b1v.w;
    };
    auto store_s = [&](int buf) {
#pragma unroll
        for (int j = 0; j < 8; j++) As[buf][akoff + j][arow] = ar[j];
        *(float4*)&Bs[buf][bk][bn]     = make_float4(br[0], br[1], br[2], br[3]);
        *(float4*)&Bs[buf][bk][bn + 4] = make_float4(br[4], br[5], br[6], br[7]);
    };

    const int NK = DFF / 16;
    loadg(0); store_s(0); __syncthreads();
    for (int kt = 0; kt < NK; kt++) {
        const int cur = kt & 1;
        if (kt + 1 < NK) loadg(kt + 1);
#pragma unroll
        for (int k = 0; k < 16; k++) {
            float4 a0 = *(const float4*)&As[cur][k][ty * 8];
            float4 a1 = *(const float4*)&As[cur][k][ty * 8 + 4];
            float4 b0 = *(const float4*)&Bs[cur][k][tx * 8];
            float4 b1v = *(const float4*)&Bs[cur][k][tx * 8 + 4];
            float av[8] = {a0.x,a0.y,a0.z,a0.w,a1.x,a1.y,a1.z,a1.w};
            float bv[8] = {b0.x,b0.y,b0.z,b0.w,b1v.x,b1v.y,b1v.z,b1v.w};
#pragma unroll
            for (int i = 0; i < 8; i++)
#pragma unroll
                for (int j = 0; j < 8; j++)
                    acc[i][j] = fmaf(av[i], bv[j], acc[i][j]);
        }
        if (kt + 1 < NK) store_s(cur ^ 1);
        __syncthreads();
    }

    // epilogue: gate-scaled scatter-add into out (2 addends/element -> deterministic)
    const float* b2e = b2 + (size_t)e * DM + n0 + tx * 8;
#pragma unroll
    for (int i = 0; i < 8; i++) {
        const int r = ty * 8 + i;
        if (m0 + r < c) {
            const int   t = g_tok[e * TOKENS + m0 + r];
            const float g = g_gate[e * TOKENS + m0 + r];
            float* op = out + (size_t)t * DM + n0 + tx * 8;
#pragma unroll
            for (int j = 0; j < 8; j++)
                atomicAdd(&op[j], g * (acc[i][j] + b2e[j]));
        }
    }
}

// ---------------- launch ----------------
extern "C" void kernel_launch(void* const* d_in, const int* in_sizes, int n_in,
                              void* d_out, int out_size) {
    const float* x  = (const float*)d_in[0];
    const float* Wg = (const float*)d_in[1];
    const float* bg = (const float*)d_in[2];
    const float* W1 = (const float*)d_in[3];
    const float* b1 = (const float*)d_in[4];
    const float* W2 = (const float*)d_in[5];
    const float* b2 = (const float*)d_in[6];
    float* out = (float*)d_out;

    cudaMemsetAsync(out, 0, (size_t)TOKENS * DM * sizeof(float));
    zero_cnt_kernel<<<1, 32>>>();
    gate_kernel<<<TOKENS / 8, 256>>>(x, Wg, bg);

    dim3 g1(DFF / 128, NE, TOKENS / 128);
    gemm1_kernel<<<g1, 256>>>(x, W1, b1);

    dim3 g2(DM / 128, NE, TOKENS / 128);
    gemm2_kernel<<<g2, 256>>>(W2, b2, out);
}

// round 4
// speedup vs baseline: 5.7335x; 5.7335x over previous
#include <cuda_runtime.h>
#include <cuda_fp16.h>
#include <math.h>
#include <stdint.h>

#define TOKENS 4096
#define DM     1024
#define DFF    4096
#define NE     8

// ---------------- static device scratch ----------------
static __device__ __half g_xh[(size_t)TOKENS * DM];            // 8 MB
static __device__ __half g_w1h[(size_t)NE * DM * DFF];         // 64 MB  [e][k][n] native
static __device__ __half g_w2h[(size_t)NE * DFF * DM];         // 64 MB  [e][k][n] native
static __device__ __half g_h[(size_t)NE * TOKENS * DFF];       // 256 MB
static __device__ float  g_y[(size_t)NE * TOKENS * DM];        // 128 MB per-slot outputs
static __device__ int    g_tok[NE * TOKENS];
static __device__ float  g_gate[NE * TOKENS];
static __device__ int    g_pos[2 * TOKENS];
static __device__ int    g_cnt[NE];

// ---------------- PTX helpers (base sm_103 ISA only!) ----------------
__device__ __forceinline__ uint32_t smem_to_u32(const void* p) {
    uint32_t a;
    asm("{ .reg .u64 t; cvta.to.shared.u64 t, %1; cvt.u32.u64 %0, t; }" : "=r"(a) : "l"(p));
    return a;
}
__device__ __forceinline__ void cp16(uint32_t dst, const void* src, uint32_t nbytes) {
    asm volatile("cp.async.ca.shared.global [%0], [%1], 16, %2;"
                 :: "r"(dst), "l"(src), "r"(nbytes) : "memory");
}
#define CP_COMMIT() asm volatile("cp.async.commit_group;" ::: "memory")
#define CP_WAIT(N)  asm volatile("cp.async.wait_group %0;" :: "n"(N) : "memory")

__device__ __forceinline__ void ldm_x4(uint32_t* r, uint32_t addr) {
    asm volatile("ldmatrix.sync.aligned.m8n8.x4.shared.b16 {%0,%1,%2,%3}, [%4];"
                 : "=r"(r[0]), "=r"(r[1]), "=r"(r[2]), "=r"(r[3]) : "r"(addr));
}
__device__ __forceinline__ void ldm_x4_t(uint32_t* r, uint32_t addr) {
    asm volatile("ldmatrix.sync.aligned.m8n8.x4.trans.shared.b16 {%0,%1,%2,%3}, [%4];"
                 : "=r"(r[0]), "=r"(r[1]), "=r"(r[2]), "=r"(r[3]) : "r"(addr));
}
__device__ __forceinline__ void mma16816(float* d, const uint32_t* a, uint32_t b0, uint32_t b1) {
    asm volatile(
        "mma.sync.aligned.m16n8k16.row.col.f32.f16.f16.f32 "
        "{%0,%1,%2,%3}, {%4,%5,%6,%7}, {%8,%9}, {%0,%1,%2,%3};"
        : "+f"(d[0]), "+f"(d[1]), "+f"(d[2]), "+f"(d[3])
        : "r"(a[0]), "r"(a[1]), "r"(a[2]), "r"(a[3]), "r"(b0), "r"(b1));
}

__device__ __forceinline__ float gelu_f(float v) {
    float v3 = v * v * v;
    return 0.5f * v * (1.f + tanhf(0.7978845608028654f * (v + 0.044715f * v3)));
}

// ---------------- small kernels ----------------
__global__ void zero_cnt_kernel() { if (threadIdx.x < NE) g_cnt[threadIdx.x] = 0; }

__global__ void gate_kernel(const float* __restrict__ x,
                            const float* __restrict__ Wg,
                            const float* __restrict__ bg) {
    __shared__ float sWg[DM * NE];
    const int tid = threadIdx.x;
    for (int i = tid; i < DM * NE; i += 256) sWg[i] = Wg[i];
    __syncthreads();
    const int warp = tid >> 5, lane = tid & 31;
    const int t = blockIdx.x * 8 + warp;
    const float* xr = x + (size_t)t * DM;
    float acc[NE];
#pragma unroll
    for (int e = 0; e < NE; e++) acc[e] = 0.f;
    for (int i = 0; i < DM / 32; i++) {
        const int r = i * 32 + lane;
        const float xv = xr[r];
#pragma unroll
        for (int e = 0; e < NE; e++) acc[e] += xv * sWg[r * NE + e];
    }
#pragma unroll
    for (int e = 0; e < NE; e++)
#pragma unroll
        for (int off = 16; off > 0; off >>= 1)
            acc[e] += __shfl_xor_sync(0xFFFFFFFFu, acc[e], off);
    if (lane == 0) {
        float v[NE];
#pragma unroll
        for (int e = 0; e < NE; e++) v[e] = acc[e] + bg[e];
        int b0 = 0; float m0v = v[0];
#pragma unroll
        for (int e = 1; e < NE; e++) if (v[e] > m0v) { m0v = v[e]; b0 = e; }
        int b1i = (b0 == 0) ? 1 : 0; float m1v = v[(b0 == 0) ? 1 : 0];
#pragma unroll
        for (int e = 0; e < NE; e++)
            if (e != b0 && v[e] > m1v) { m1v = v[e]; b1i = e; }
        const float e1 = expf(m1v - m0v);
        const float s = 1.f + e1;
        int p = atomicAdd(&g_cnt[b0], 1);
        g_tok[b0 * TOKENS + p] = t; g_gate[b0 * TOKENS + p] = 1.f / s;
        g_pos[2 * t] = b0 * TOKENS + p;
        p = atomicAdd(&g_cnt[b1i], 1);
        g_tok[b1i * TOKENS + p] = t; g_gate[b1i * TOKENS + p] = e1 / s;
        g_pos[2 * t + 1] = b1i * TOKENS + p;
    }
}

__global__ void convert_x_kernel(const float* __restrict__ x) {
    const int i = blockIdx.x * blockDim.x + threadIdx.x;
    float4 a = ((const float4*)x)[2 * i];
    float4 b = ((const float4*)x)[2 * i + 1];
    __half h[8] = { __float2half_rn(a.x), __float2half_rn(a.y),
                    __float2half_rn(a.z), __float2half_rn(a.w),
                    __float2half_rn(b.x), __float2half_rn(b.y),
                    __float2half_rn(b.z), __float2half_rn(b.w) };
    ((uint4*)g_xh)[i] = *(uint4*)h;
}

template<int W>   // 1 -> g_w1h, 2 -> g_w2h
__global__ void convert_w_kernel(const float* __restrict__ src) {
    const size_t i = (size_t)blockIdx.x * blockDim.x + threadIdx.x;
    float4 a = ((const float4*)src)[2 * i];
    float4 b = ((const float4*)src)[2 * i + 1];
    __half h[8] = { __float2half_rn(a.x), __float2half_rn(a.y),
                    __float2half_rn(a.z), __float2half_rn(a.w),
                    __float2half_rn(b.x), __float2half_rn(b.y),
                    __float2half_rn(b.z), __float2half_rn(b.w) };
    ((uint4*)((W == 1) ? g_w1h : g_w2h))[i] = *(uint4*)h;
}

__global__ void combine_kernel(float* __restrict__ out) {
    const int t = blockIdx.x;
    const int p0 = g_pos[2 * t], p1 = g_pos[2 * t + 1];
    const float ga = g_gate[p0], gb = g_gate[p1];
    const float4* y0 = (const float4*)(g_y + (size_t)p0 * DM);
    const float4* y1 = (const float4*)(g_y + (size_t)p1 * DM);
    float4* o = (float4*)(out + (size_t)t * DM);
    const int i = threadIdx.x;   // 256 threads, DM/4 = 256
    float4 a = y0[i], b = y1[i];
    o[i] = make_float4(ga * a.x + gb * b.x, ga * a.y + gb * b.y,
                       ga * a.z + gb * b.z, ga * a.w + gb * b.w);
}

// ---------------- grouped GEMMs via mma.sync (HMMA) ----------------
// Tile: 128 (slots) x 128 (cols), K-chunk 32, double-buffered cp.async.
// 8 warps: warp_m = wid>>2 (2 x 64 rows), warp_n = wid&3 (4 x 32 cols).
// PHASE 1: h = gelu(x[tok] @ W1 + b1) -> g_h (fp16)
// PHASE 2: y[slot] = h[slot] @ W2 + b2 -> g_y (fp32)
#define ASTRIDE 40
#define BSTRIDE 136
#define ASTAGE  (128 * ASTRIDE * 2)
#define BSTAGE  (32 * BSTRIDE * 2)
#define SMEM_GEMM (2 * ASTAGE + 2 * BSTAGE)

template<int PHASE>
__global__ void __launch_bounds__(256, 2)
moe_gemm_kernel(const float* __restrict__ bias_g, float* __restrict__ dummy) {
    constexpr int KDIM = (PHASE == 1) ? DM : DFF;
    constexpr int NDIM = (PHASE == 1) ? DFF : DM;
    constexpr int NK = KDIM / 32;

    const int e  = blockIdx.y;
    const int c  = g_cnt[e];
    const int m0 = blockIdx.z * 128;
    if (m0 >= c) return;
    const int n0 = blockIdx.x * 128;

    extern __shared__ __align__(1024) char smem[];
    const uint32_t su = smem_to_u32(smem);
    const uint32_t sA = su, sB = su + 2 * ASTAGE;

    const int tid = threadIdx.x;
    const int wid = tid >> 5, lane = tid & 31;
    const int warp_m = wid >> 2, warp_n = wid & 3;

    // ---- global source pointers ----
    const int arow = tid >> 1, ac0 = (tid & 1) * 2;      // A: 2 x 16B per thread
    const int slotA = m0 + arow;
    const bool avalid = slotA < c;
    const __half* aptr;
    if (PHASE == 1) {
        const int tok = avalid ? g_tok[e * TOKENS + slotA] : 0;
        aptr = g_xh + (size_t)tok * DM;
    } else {
        aptr = g_h + ((size_t)e * TOKENS + (avalid ? slotA : 0)) * DFF;
    }
    const uint32_t abytes = (PHASE == 2 || avalid) ? 16u : 0u;

    const int brow = tid >> 3, bc0 = (tid & 7) * 2;      // B: 2 x 16B per thread
    const __half* bbase = ((PHASE == 1) ? g_w1h : g_w2h)
                        + (size_t)e * KDIM * NDIM + n0;

    auto load_stage = [&](int kt, int s) {
        const uint32_t ad = sA + s * ASTAGE + (arow * ASTRIDE + ac0 * 8) * 2;
        const __half* as = aptr + kt * 32 + ac0 * 8;
        cp16(ad, as, abytes);
        cp16(ad + 16, as + 8, abytes);
        const uint32_t bd = sB + s * BSTAGE + (brow * BSTRIDE + bc0 * 8) * 2;
        const __half* bs = bbase + (size_t)(kt * 32 + brow) * NDIM + bc0 * 8;
        cp16(bd, bs, 16);
        cp16(bd + 16, bs + 8, 16);
        CP_COMMIT();
    };

    float acc[4][4][4];
#pragma unroll
    for (int i = 0; i < 4; i++)
#pragma unroll
        for (int j = 0; j < 4; j++)
#pragma unroll
            for (int q = 0; q < 4; q++) acc[i][j][q] = 0.f;

    auto compute_stage = [&](int s) {
        const uint32_t ab = sA + s * ASTAGE;
        const uint32_t bb = sB + s * BSTAGE;
#pragma unroll
        for (int ks = 0; ks < 2; ks++) {
            uint32_t af[4][4];
#pragma unroll
            for (int mt = 0; mt < 4; mt++) {
                const uint32_t addr = ab +
                    ((warp_m * 64 + mt * 16 + (lane & 15)) * ASTRIDE +
                     ks * 16 + (lane >> 4) * 8) * 2;
                ldm_x4(af[mt], addr);
            }
            uint32_t bf[2][4];
#pragma unroll
            for (int np = 0; np < 2; np++) {
                const uint32_t k = ks * 16 + (lane & 7) + ((lane >> 3) & 1) * 8;
                const uint32_t col = warp_n * 32 + np * 16 + (lane >> 4) * 8;
                ldm_x4_t(bf[np], bb + (k * BSTRIDE + col) * 2);
            }
#pragma unroll
            for (int mt = 0; mt < 4; mt++)
#pragma unroll
                for (int nt = 0; nt < 4; nt++)
                    mma16816(acc[mt][nt], af[mt],
                             bf[nt >> 1][(nt & 1) * 2], bf[nt >> 1][(nt & 1) * 2 + 1]);
        }
    };

    load_stage(0, 0);
    for (int kt = 0; kt < NK; kt++) {
        const int cur = kt & 1;
        if (kt + 1 < NK) { load_stage(kt + 1, cur ^ 1); CP_WAIT(1); }
        else             { CP_WAIT(0); }
        __syncthreads();
        compute_stage(cur);
        __syncthreads();
    }

    // ---- epilogue ----
    const float* bias = bias_g + (size_t)e * NDIM;
#pragma unroll
    for (int mt = 0; mt < 4; mt++) {
#pragma unroll
        for (int rh = 0; rh < 2; rh++) {
            const int r = warp_m * 64 + mt * 16 + (lane >> 2) + rh * 8;
            const int slot = m0 + r;
            if (slot < c) {
#pragma unroll
                for (int nt = 0; nt < 4; nt++) {
                    const int col = n0 + warp_n * 32 + nt * 8 + (lane & 3) * 2;
                    const float v0 = acc[mt][nt][rh * 2 + 0] + __ldg(&bias[col]);
                    const float v1 = acc[mt][nt][rh * 2 + 1] + __ldg(&bias[col + 1]);
                    if (PHASE == 1) {
                        __half2 hv = __floats2half2_rn(gelu_f(v0), gelu_f(v1));
                        *(__half2*)(g_h + ((size_t)e * TOKENS + slot) * DFF + col) = hv;
                    } else {
                        *(float2*)(g_y + ((size_t)e * TOKENS + slot) * DM + col) =
                            make_float2(v0, v1);
                    }
                }
            }
        }
    }
}

// ---------------- launch ----------------
extern "C" void kernel_launch(void* const* d_in, const int* in_sizes, int n_in,
                              void* d_out, int out_size) {
    const float* x  = (const float*)d_in[0];
    const float* Wg = (const float*)d_in[1];
    const float* bg = (const float*)d_in[2];
    const float* W1 = (const float*)d_in[3];
    const float* b1 = (const float*)d_in[4];
    const float* W2 = (const float*)d_in[5];
    const float* b2 = (const float*)d_in[6];
    float* out = (float*)d_out;

    zero_cnt_kernel<<<1, 32>>>();
    gate_kernel<<<TOKENS / 8, 256>>>(x, Wg, bg);
    convert_x_kernel<<<(TOKENS * DM / 8) / 256, 256>>>(x);
    convert_w_kernel<1><<<(NE * (size_t)DM * DFF / 8) / 256, 256>>>(W1);
    convert_w_kernel<2><<<(NE * (size_t)DFF * DM / 8) / 256, 256>>>(W2);

    dim3 g1(DFF / 128, NE, TOKENS / 128);
    moe_gemm_kernel<1><<<g1, 256, SMEM_GEMM>>>(b1, nullptr);
    dim3 g2(DM / 128, NE, TOKENS / 128);
    moe_gemm_kernel<2><<<g2, 256, SMEM_GEMM>>>(b2, nullptr);

    combine_kernel<<<TOKENS, 256>>>(out);
}

// round 5
// speedup vs baseline: 5.8553x; 1.0213x over previous
#include <cuda_runtime.h>
#include <cuda_fp16.h>
#include <math.h>
#include <stdint.h>

#define TOKENS 4096
#define DM     1024
#define DFF    4096
#define NE     8

// ---------------- static device scratch ----------------
static __device__ __half g_xh[(size_t)TOKENS * DM];            // 8 MB
static __device__ __half g_h[(size_t)NE * TOKENS * DFF];       // 256 MB
static __device__ float  g_y[(size_t)NE * TOKENS * DM];        // 128 MB per-slot outputs
static __device__ int    g_tok[NE * TOKENS];
static __device__ float  g_gate[NE * TOKENS];
static __device__ int    g_pos[2 * TOKENS];
static __device__ int    g_cnt[NE];

// ---------------- PTX helpers (base sm_103 ISA only) ----------------
__device__ __forceinline__ uint32_t smem_to_u32(const void* p) {
    uint32_t a;
    asm("{ .reg .u64 t; cvta.to.shared.u64 t, %1; cvt.u32.u64 %0, t; }" : "=r"(a) : "l"(p));
    return a;
}
__device__ __forceinline__ void cp16(uint32_t dst, const void* src, uint32_t nbytes) {
    asm volatile("cp.async.ca.shared.global [%0], [%1], 16, %2;"
                 :: "r"(dst), "l"(src), "r"(nbytes) : "memory");
}
#define CP_COMMIT() asm volatile("cp.async.commit_group;" ::: "memory")
#define CP_WAIT(N)  asm volatile("cp.async.wait_group %0;" :: "n"(N) : "memory")

__device__ __forceinline__ void ldm_x4(uint32_t* r, uint32_t addr) {
    asm volatile("ldmatrix.sync.aligned.m8n8.x4.shared.b16 {%0,%1,%2,%3}, [%4];"
                 : "=r"(r[0]), "=r"(r[1]), "=r"(r[2]), "=r"(r[3]) : "r"(addr));
}
__device__ __forceinline__ void ldm_x4_t(uint32_t* r, uint32_t addr) {
    asm volatile("ldmatrix.sync.aligned.m8n8.x4.trans.shared.b16 {%0,%1,%2,%3}, [%4];"
                 : "=r"(r[0]), "=r"(r[1]), "=r"(r[2]), "=r"(r[3]) : "r"(addr));
}
__device__ __forceinline__ void mma16816(float* d, const uint32_t* a, uint32_t b0, uint32_t b1) {
    asm volatile(
        "mma.sync.aligned.m16n8k16.row.col.f32.f16.f16.f32 "
        "{%0,%1,%2,%3}, {%4,%5,%6,%7}, {%8,%9}, {%0,%1,%2,%3};"
        : "+f"(d[0]), "+f"(d[1]), "+f"(d[2]), "+f"(d[3])
        : "r"(a[0]), "r"(a[1]), "r"(a[2]), "r"(a[3]), "r"(b0), "r"(b1));
}

__device__ __forceinline__ float gelu_f(float v) {
    float v3 = v * v * v;
    return 0.5f * v * (1.f + tanhf(0.7978845608028654f * (v + 0.044715f * v3)));
}

// ---------------- small kernels ----------------
__global__ void zero_cnt_kernel() { if (threadIdx.x < NE) g_cnt[threadIdx.x] = 0; }

__global__ void gate_kernel(const float* __restrict__ x,
                            const float* __restrict__ Wg,
                            const float* __restrict__ bg) {
    __shared__ float sWg[DM * NE];
    const int tid = threadIdx.x;
    for (int i = tid; i < DM * NE; i += 256) sWg[i] = Wg[i];
    __syncthreads();
    const int warp = tid >> 5, lane = tid & 31;
    const int t = blockIdx.x * 8 + warp;
    const float* xr = x + (size_t)t * DM;
    float acc[NE];
#pragma unroll
    for (int e = 0; e < NE; e++) acc[e] = 0.f;
    for (int i = 0; i < DM / 32; i++) {
        const int r = i * 32 + lane;
        const float xv = xr[r];
#pragma unroll
        for (int e = 0; e < NE; e++) acc[e] += xv * sWg[r * NE + e];
    }
#pragma unroll
    for (int e = 0; e < NE; e++)
#pragma unroll
        for (int off = 16; off > 0; off >>= 1)
            acc[e] += __shfl_xor_sync(0xFFFFFFFFu, acc[e], off);
    if (lane == 0) {
        float v[NE];
#pragma unroll
        for (int e = 0; e < NE; e++) v[e] = acc[e] + bg[e];
        int b0 = 0; float m0v = v[0];
#pragma unroll
        for (int e = 1; e < NE; e++) if (v[e] > m0v) { m0v = v[e]; b0 = e; }
        int b1i = (b0 == 0) ? 1 : 0; float m1v = v[(b0 == 0) ? 1 : 0];
#pragma unroll
        for (int e = 0; e < NE; e++)
            if (e != b0 && v[e] > m1v) { m1v = v[e]; b1i = e; }
        const float e1 = expf(m1v - m0v);
        const float s = 1.f + e1;
        int p = atomicAdd(&g_cnt[b0], 1);
        g_tok[b0 * TOKENS + p] = t; g_gate[b0 * TOKENS + p] = 1.f / s;
        g_pos[2 * t] = b0 * TOKENS + p;
        p = atomicAdd(&g_cnt[b1i], 1);
        g_tok[b1i * TOKENS + p] = t; g_gate[b1i * TOKENS + p] = e1 / s;
        g_pos[2 * t + 1] = b1i * TOKENS + p;
    }
}

__global__ void convert_x_kernel(const float* __restrict__ x) {
    const int i = blockIdx.x * blockDim.x + threadIdx.x;
    float4 a = ((const float4*)x)[2 * i];
    float4 b = ((const float4*)x)[2 * i + 1];
    __half h[8] = { __float2half_rn(a.x), __float2half_rn(a.y),
                    __float2half_rn(a.z), __float2half_rn(a.w),
                    __float2half_rn(b.x), __float2half_rn(b.y),
                    __float2half_rn(b.z), __float2half_rn(b.w) };
    ((uint4*)g_xh)[i] = *(uint4*)h;
}

__global__ void combine_kernel(float* __restrict__ out) {
    const int t = blockIdx.x;
    const int p0 = g_pos[2 * t], p1 = g_pos[2 * t + 1];
    const float ga = g_gate[p0], gb = g_gate[p1];
    const float4* y0 = (const float4*)(g_y + (size_t)p0 * DM);
    const float4* y1 = (const float4*)(g_y + (size_t)p1 * DM);
    float4* o = (float4*)(out + (size_t)t * DM);
    const int i = threadIdx.x;
    float4 a = y0[i], b = y1[i];
    o[i] = make_float4(ga * a.x + gb * b.x, ga * a.y + gb * b.y,
                       ga * a.z + gb * b.z, ga * a.w + gb * b.w);
}

// ---------------- grouped GEMMs via mma.sync (HMMA), fused W fp32->fp16 ----------------
// Tile: 128 (slots) x 128 (cols), K-chunk 32, double-buffered.
// A (fp16): cp.async.  B (fp32 weights): LDG.128 -> cvt fp16 -> STS (reg prefetch).
// 8 warps: warp_m = wid>>2 (2 x 64 rows), warp_n = wid&3 (4 x 32 cols).
#define ASTRIDE 40
#define BSTRIDE 136
#define ASTAGE  (128 * ASTRIDE * 2)
#define BSTAGE  (32 * BSTRIDE * 2)
#define SMEM_GEMM (2 * ASTAGE + 2 * BSTAGE)

template<int PHASE>
__global__ void __launch_bounds__(256, 2)
moe_gemm_kernel(const float* __restrict__ Wg32,   // fp32 weights [e][K][N]
                const float* __restrict__ bias_g) {
    constexpr int KDIM = (PHASE == 1) ? DM : DFF;
    constexpr int NDIM = (PHASE == 1) ? DFF : DM;
    constexpr int NK = KDIM / 32;

    const int e  = blockIdx.y;
    const int c  = g_cnt[e];
    const int m0 = blockIdx.z * 128;
    if (m0 >= c) return;
    const int n0 = blockIdx.x * 128;

    extern __shared__ __align__(1024) char smem[];
    const uint32_t su = smem_to_u32(smem);
    const uint32_t sA = su, sB = su + 2 * ASTAGE;

    const int tid = threadIdx.x;
    const int wid = tid >> 5, lane = tid & 31;
    const int warp_m = wid >> 2, warp_n = wid & 3;

    // ---- A source (fp16, cp.async): row = tid>>1, 2 x 16B per thread ----
    const int arow = tid >> 1, ac0 = (tid & 1) * 2;
    const int slotA = m0 + arow;
    const bool avalid = slotA < c;
    const __half* aptr;
    if (PHASE == 1) {
        const int tok = avalid ? g_tok[e * TOKENS + slotA] : 0;
        aptr = g_xh + (size_t)tok * DM;
    } else {
        aptr = g_h + ((size_t)e * TOKENS + (avalid ? slotA : 0)) * DFF;
    }
    const uint32_t abytes = (PHASE == 2 || avalid) ? 16u : 0u;

    auto loadA = [&](int kt, int s) {
        const uint32_t ad = sA + s * ASTAGE + (arow * ASTRIDE + ac0 * 8) * 2;
        const __half* as = aptr + kt * 32 + ac0 * 8;
        cp16(ad, as, abytes);
        cp16(ad + 16, as + 8, abytes);
        CP_COMMIT();
    };

    // ---- B source (fp32 weights, LDG + cvt): row = tid>>3 (32 rows),
    //      float4 idx f = (tid&7) + 8*i, i in [0,4) ----
    const int brow = tid >> 3, bf4 = tid & 7;
    const float* bbase = Wg32 + (size_t)e * KDIM * NDIM + n0;
    float4 breg[4];

    auto ldgB = [&](int kt) {
        const float4* src = (const float4*)(bbase + (size_t)(kt * 32 + brow) * NDIM);
#pragma unroll
        for (int i = 0; i < 4; i++) breg[i] = __ldg(&src[bf4 + 8 * i]);
    };
    auto stsB = [&](int s) {
        const uint32_t base = sB + s * BSTAGE + (brow * BSTRIDE) * 2;
#pragma unroll
        for (int i = 0; i < 4; i++) {
            __half2 h01 = __floats2half2_rn(breg[i].x, breg[i].y);
            __half2 h23 = __floats2half2_rn(breg[i].z, breg[i].w);
            const uint32_t addr = base + (bf4 + 8 * i) * 4 * 2;
            asm volatile("st.shared.v2.b32 [%0], {%1, %2};"
                         :: "r"(addr), "r"(*(uint32_t*)&h01), "r"(*(uint32_t*)&h23)
                         : "memory");
        }
    };

    float acc[4][4][4];
#pragma unroll
    for (int i = 0; i < 4; i++)
#pragma unroll
        for (int j = 0; j < 4; j++)
#pragma unroll
            for (int q = 0; q < 4; q++) acc[i][j][q] = 0.f;

    auto compute_stage = [&](int s) {
        const uint32_t ab = sA + s * ASTAGE;
        const uint32_t bb = sB + s * BSTAGE;
#pragma unroll
        for (int ks = 0; ks < 2; ks++) {
            uint32_t af[4][4];
#pragma unroll
            for (int mt = 0; mt < 4; mt++) {
                const uint32_t addr = ab +
                    ((warp_m * 64 + mt * 16 + (lane & 15)) * ASTRIDE +
                     ks * 16 + (lane >> 4) * 8) * 2;
                ldm_x4(af[mt], addr);
            }
            uint32_t bf[2][4];
#pragma unroll
            for (int np = 0; np < 2; np++) {
                const uint32_t k = ks * 16 + (lane & 7) + ((lane >> 3) & 1) * 8;
                const uint32_t col = warp_n * 32 + np * 16 + (lane >> 4) * 8;
                ldm_x4_t(bf[np], bb + (k * BSTRIDE + col) * 2);
            }
#pragma unroll
            for (int mt = 0; mt < 4; mt++)
#pragma unroll
                for (int nt = 0; nt < 4; nt++)
                    mma16816(acc[mt][nt], af[mt],
                             bf[nt >> 1][(nt & 1) * 2], bf[nt >> 1][(nt & 1) * 2 + 1]);
        }
    };

    // ---- pipeline: breg prefetched 0; per iter: STS(cur), prefetch kt+1, compute ----
    ldgB(0);
    loadA(0, 0);                       // group 0
    for (int kt = 0; kt < NK; kt++) {
        const int cur = kt & 1;
        stsB(cur);                     // breg holds kt
        if (kt + 1 < NK) {
            loadA(kt + 1, cur ^ 1);    // group kt+1
            ldgB(kt + 1);              // prefetch next B into regs
            CP_WAIT(1);                // A(kt) arrived
        } else {
            CP_WAIT(0);
        }
        __syncthreads();               // stage cur (A + B) visible to all
        compute_stage(cur);
        __syncthreads();               // stage cur free for kt+2
    }

    // ---- epilogue ----
    const float* bias = bias_g + (size_t)e * NDIM;
#pragma unroll
    for (int mt = 0; mt < 4; mt++) {
#pragma unroll
        for (int rh = 0; rh < 2; rh++) {
            const int r = warp_m * 64 + mt * 16 + (lane >> 2) + rh * 8;
            const int slot = m0 + r;
            if (slot < c) {
#pragma unroll
                for (int nt = 0; nt < 4; nt++) {
                    const int col = n0 + warp_n * 32 + nt * 8 + (lane & 3) * 2;
                    const float v0 = acc[mt][nt][rh * 2 + 0] + __ldg(&bias[col]);
                    const float v1 = acc[mt][nt][rh * 2 + 1] + __ldg(&bias[col + 1]);
                    if (PHASE == 1) {
                        __half2 hv = __floats2half2_rn(gelu_f(v0), gelu_f(v1));
                        *(__half2*)(g_h + ((size_t)e * TOKENS + slot) * DFF + col) = hv;
                    } else {
                        *(float2*)(g_y + ((size_t)e * TOKENS + slot) * DM + col) =
                            make_float2(v0, v1);
                    }
                }
            }
        }
    }
}

// ---------------- launch ----------------
extern "C" void kernel_launch(void* const* d_in, const int* in_sizes, int n_in,
                              void* d_out, int out_size) {
    const float* x  = (const float*)d_in[0];
    const float* Wg = (const float*)d_in[1];
    const float* bg = (const float*)d_in[2];
    const float* W1 = (const float*)d_in[3];
    const float* b1 = (const float*)d_in[4];
    const float* W2 = (const float*)d_in[5];
    const float* b2 = (const float*)d_in[6];
    float* out = (float*)d_out;

    zero_cnt_kernel<<<1, 32>>>();
    gate_kernel<<<TOKENS / 8, 256>>>(x, Wg, bg);
    convert_x_kernel<<<(TOKENS * DM / 8) / 256, 256>>>(x);

    dim3 g1(DFF / 128, NE, TOKENS / 128);
    moe_gemm_kernel<1><<<g1, 256, SMEM_GEMM>>>(W1, b1);
    dim3 g2(DM / 128, NE, TOKENS / 128);
    moe_gemm_kernel<2><<<g2, 256, SMEM_GEMM>>>(W2, b2);

    combine_kernel<<<TOKENS, 256>>>(out);
}

// round 6
// speedup vs baseline: 6.0954x; 1.0410x over previous
#include <cuda_runtime.h>
#include <cuda_fp16.h>
#include <math.h>
#include <stdint.h>

#define TOKENS 4096
#define DM     1024
#define DFF    4096
#define NE     8

// ---------------- static device scratch ----------------
static __device__ __half g_xh[(size_t)TOKENS * DM];            // 8 MB
static __device__ __half g_h[(size_t)NE * TOKENS * DFF];       // 256 MB
static __device__ float  g_y[(size_t)NE * TOKENS * DM];        // 128 MB per-slot outputs
static __device__ int    g_tok[NE * TOKENS];
static __device__ float  g_gate[NE * TOKENS];
static __device__ int    g_pos[2 * TOKENS];
static __device__ int    g_cnt[NE];

// ---------------- PTX helpers (base sm_103 ISA only) ----------------
__device__ __forceinline__ uint32_t smem_to_u32(const void* p) {
    uint32_t a;
    asm("{ .reg .u64 t; cvta.to.shared.u64 t, %1; cvt.u32.u64 %0, t; }" : "=r"(a) : "l"(p));
    return a;
}
__device__ __forceinline__ void cp16(uint32_t dst, const void* src, uint32_t nbytes) {
    asm volatile("cp.async.ca.shared.global [%0], [%1], 16, %2;"
                 :: "r"(dst), "l"(src), "r"(nbytes) : "memory");
}
#define CP_COMMIT() asm volatile("cp.async.commit_group;" ::: "memory")

__device__ __forceinline__ void ldm_x4(uint32_t* r, uint32_t addr) {
    asm volatile("ldmatrix.sync.aligned.m8n8.x4.shared.b16 {%0,%1,%2,%3}, [%4];"
                 : "=r"(r[0]), "=r"(r[1]), "=r"(r[2]), "=r"(r[3]) : "r"(addr));
}
__device__ __forceinline__ void ldm_x4_t(uint32_t* r, uint32_t addr) {
    asm volatile("ldmatrix.sync.aligned.m8n8.x4.trans.shared.b16 {%0,%1,%2,%3}, [%4];"
                 : "=r"(r[0]), "=r"(r[1]), "=r"(r[2]), "=r"(r[3]) : "r"(addr));
}
__device__ __forceinline__ void mma16816(float* d, const uint32_t* a, uint32_t b0, uint32_t b1) {
    asm volatile(
        "mma.sync.aligned.m16n8k16.row.col.f32.f16.f16.f32 "
        "{%0,%1,%2,%3}, {%4,%5,%6,%7}, {%8,%9}, {%0,%1,%2,%3};"
        : "+f"(d[0]), "+f"(d[1]), "+f"(d[2]), "+f"(d[3])
        : "r"(a[0]), "r"(a[1]), "r"(a[2]), "r"(a[3]), "r"(b0), "r"(b1));
}

__device__ __forceinline__ float gelu_f(float v) {
    float v3 = v * v * v;
    return 0.5f * v * (1.f + tanhf(0.7978845608028654f * (v + 0.044715f * v3)));
}

// ---------------- small kernels ----------------
__global__ void zero_cnt_kernel() { if (threadIdx.x < NE) g_cnt[threadIdx.x] = 0; }

__global__ void gate_kernel(const float* __restrict__ x,
                            const float* __restrict__ Wg,
                            const float* __restrict__ bg) {
    __shared__ float sWg[DM * NE];
    const int tid = threadIdx.x;
    for (int i = tid; i < DM * NE; i += 256) sWg[i] = Wg[i];
    __syncthreads();
    const int warp = tid >> 5, lane = tid & 31;
    const int t = blockIdx.x * 8 + warp;
    const float* xr = x + (size_t)t * DM;
    float acc[NE];
#pragma unroll
    for (int e = 0; e < NE; e++) acc[e] = 0.f;
    for (int i = 0; i < DM / 32; i++) {
        const int r = i * 32 + lane;
        const float xv = xr[r];
#pragma unroll
        for (int e = 0; e < NE; e++) acc[e] += xv * sWg[r * NE + e];
    }
#pragma unroll
    for (int e = 0; e < NE; e++)
#pragma unroll
        for (int off = 16; off > 0; off >>= 1)
            acc[e] += __shfl_xor_sync(0xFFFFFFFFu, acc[e], off);
    if (lane == 0) {
        float v[NE];
#pragma unroll
        for (int e = 0; e < NE; e++) v[e] = acc[e] + bg[e];
        int b0 = 0; float m0v = v[0];
#pragma unroll
        for (int e = 1; e < NE; e++) if (v[e] > m0v) { m0v = v[e]; b0 = e; }
        int b1i = (b0 == 0) ? 1 : 0; float m1v = v[(b0 == 0) ? 1 : 0];
#pragma unroll
        for (int e = 0; e < NE; e++)
            if (e != b0 && v[e] > m1v) { m1v = v[e]; b1i = e; }
        const float e1 = expf(m1v - m0v);
        const float s = 1.f + e1;
        int p = atomicAdd(&g_cnt[b0], 1);
        g_tok[b0 * TOKENS + p] = t; g_gate[b0 * TOKENS + p] = 1.f / s;
        g_pos[2 * t] = b0 * TOKENS + p;
        p = atomicAdd(&g_cnt[b1i], 1);
        g_tok[b1i * TOKENS + p] = t; g_gate[b1i * TOKENS + p] = e1 / s;
        g_pos[2 * t + 1] = b1i * TOKENS + p;
    }
}

__global__ void convert_x_kernel(const float* __restrict__ x) {
    const int i = blockIdx.x * blockDim.x + threadIdx.x;
    float4 a = ((const float4*)x)[2 * i];
    float4 b = ((const float4*)x)[2 * i + 1];
    __half h[8] = { __float2half_rn(a.x), __float2half_rn(a.y),
                    __float2half_rn(a.z), __float2half_rn(a.w),
                    __float2half_rn(b.x), __float2half_rn(b.y),
                    __float2half_rn(b.z), __float2half_rn(b.w) };
    ((uint4*)g_xh)[i] = *(uint4*)h;
}

__global__ void combine_kernel(float* __restrict__ out) {
    const int t = blockIdx.x;
    const int p0 = g_pos[2 * t], p1 = g_pos[2 * t + 1];
    const float ga = g_gate[p0], gb = g_gate[p1];
    const float4* y0 = (const float4*)(g_y + (size_t)p0 * DM);
    const float4* y1 = (const float4*)(g_y + (size_t)p1 * DM);
    float4* o = (float4*)(out + (size_t)t * DM);
    const int i = threadIdx.x;
    float4 a = y0[i], b = y1[i];
    o[i] = make_float4(ga * a.x + gb * b.x, ga * a.y + gb * b.y,
                       ga * a.z + gb * b.z, ga * a.w + gb * b.w);
}

// ---------------- grouped GEMMs via mma.sync (HMMA), fused W fp32->fp16 ----------------
// Tile: 128 (slots) x 128 (cols), K-chunk 32.
// 3-stage smem pipeline, ONE __syncthreads per chunk.
// Grid: x = m-block (innermost -> weight-slice L2 reuse), y = expert, z = n-block.
// A (fp16): cp.async.  B (fp32 weights): LDG.128 -> cvt fp16 -> STS.
#define ASTRIDE 40
#define BSTRIDE 136
#define ASTAGE  (128 * ASTRIDE * 2)
#define BSTAGE  (32 * BSTRIDE * 2)
#define SMEM_GEMM (3 * (ASTAGE + BSTAGE))

template<int PHASE>
__global__ void __launch_bounds__(256, 2)
moe_gemm_kernel(const float* __restrict__ Wg32,   // fp32 weights [e][K][N]
                const float* __restrict__ bias_g) {
    constexpr int KDIM = (PHASE == 1) ? DM : DFF;
    constexpr int NDIM = (PHASE == 1) ? DFF : DM;
    constexpr int NK = KDIM / 32;

    const int e  = blockIdx.y;
    const int c  = g_cnt[e];
    const int m0 = blockIdx.x * 128;          // m innermost
    if (m0 >= c) return;
    const int n0 = blockIdx.z * 128;          // n outermost

    extern __shared__ __align__(1024) char smem[];
    const uint32_t su = smem_to_u32(smem);
    const uint32_t sA = su, sB = su + 3 * ASTAGE;

    const int tid = threadIdx.x;
    const int wid = tid >> 5, lane = tid & 31;
    const int warp_m = wid >> 2, warp_n = wid & 3;

    // ---- A source (fp16, cp.async): row = tid>>1, 2 x 16B per thread ----
    const int arow = tid >> 1, ac0 = (tid & 1) * 2;
    const int slotA = m0 + arow;
    const bool avalid = slotA < c;
    const __half* aptr;
    if (PHASE == 1) {
        const int tok = avalid ? g_tok[e * TOKENS + slotA] : 0;
        aptr = g_xh + (size_t)tok * DM;
    } else {
        aptr = g_h + ((size_t)e * TOKENS + (avalid ? slotA : 0)) * DFF;
    }
    const uint32_t abytes = (PHASE == 2 || avalid) ? 16u : 0u;

    auto loadA = [&](int kt, int s) {
        const uint32_t ad = sA + s * ASTAGE + (arow * ASTRIDE + ac0 * 8) * 2;
        const __half* as = aptr + kt * 32 + ac0 * 8;
        cp16(ad, as, abytes);
        cp16(ad + 16, as + 8, abytes);
        CP_COMMIT();
    };

    // ---- B source (fp32 weights): row = tid>>3 (32 rows), 4 x float4 ----
    const int brow = tid >> 3, bf4 = tid & 7;
    const float* bbase = Wg32 + (size_t)e * KDIM * NDIM + n0;
    float4 breg[4];

    auto ldgB = [&](int kt) {
        const float4* src = (const float4*)(bbase + (size_t)(kt * 32 + brow) * NDIM);
#pragma unroll
        for (int i = 0; i < 4; i++) breg[i] = __ldg(&src[bf4 + 8 * i]);
    };
    auto stsB = [&](int s) {
        const uint32_t base = sB + s * BSTAGE + (brow * BSTRIDE) * 2;
#pragma unroll
        for (int i = 0; i < 4; i++) {
            __half2 h01 = __floats2half2_rn(breg[i].x, breg[i].y);
            __half2 h23 = __floats2half2_rn(breg[i].z, breg[i].w);
            const uint32_t addr = base + (bf4 + 8 * i) * 4 * 2;
            asm volatile("st.shared.v2.b32 [%0], {%1, %2};"
                         :: "r"(addr), "r"(*(uint32_t*)&h01), "r"(*(uint32_t*)&h23)
                         : "memory");
        }
    };

    float acc[4][4][4];
#pragma unroll
    for (int i = 0; i < 4; i++)
#pragma unroll
        for (int j = 0; j < 4; j++)
#pragma unroll
            for (int q = 0; q < 4; q++) acc[i][j][q] = 0.f;

    auto compute_stage = [&](int s) {
        const uint32_t ab = sA + s * ASTAGE;
        const uint32_t bb = sB + s * BSTAGE;
#pragma unroll
        for (int ks = 0; ks < 2; ks++) {
            uint32_t af[4][4];
#pragma unroll
            for (int mt = 0; mt < 4; mt++) {
                const uint32_t addr = ab +
                    ((warp_m * 64 + mt * 16 + (lane & 15)) * ASTRIDE +
                     ks * 16 + (lane >> 4) * 8) * 2;
                ldm_x4(af[mt], addr);
            }
            uint32_t bf[2][4];
#pragma unroll
            for (int np = 0; np < 2; np++) {
                const uint32_t k = ks * 16 + (lane & 7) + ((lane >> 3) & 1) * 8;
                const uint32_t col = warp_n * 32 + np * 16 + (lane >> 4) * 8;
                ldm_x4_t(bf[np], bb + (k * BSTRIDE + col) * 2);
            }
#pragma unroll
            for (int mt = 0; mt < 4; mt++)
#pragma unroll
                for (int nt = 0; nt < 4; nt++)
                    mma16816(acc[mt][nt], af[mt],
                             bf[nt >> 1][(nt & 1) * 2], bf[nt >> 1][(nt & 1) * 2 + 1]);
        }
    };

    // ---- prologue: fill stages 0 and 1 ----
    ldgB(0); stsB(0); loadA(0, 0);      // group 0
    ldgB(1); stsB(1); loadA(1, 1);      // group 1

    // ---- mainloop: one sync per chunk, 3 stages ----
    for (int kt = 0; kt < NK; kt++) {
        const int s = kt % 3;
        if (kt + 1 < NK) { asm volatile("cp.async.wait_group 1;" ::: "memory"); }
        else             { asm volatile("cp.async.wait_group 0;" ::: "memory"); }
        __syncthreads();                 // A(kt) visible; stage (kt+2)%3 free
        if (kt + 2 < NK) ldgB(kt + 2);   // issue LDG early (hidden under compute)
        compute_stage(s);
        if (kt + 2 < NK) { stsB((kt + 2) % 3); loadA(kt + 2, (kt + 2) % 3); }
    }

    // ---- epilogue ----
    const float* bias = bias_g + (size_t)e * NDIM;
#pragma unroll
    for (int mt = 0; mt < 4; mt++) {
#pragma unroll
        for (int rh = 0; rh < 2; rh++) {
            const int r = warp_m * 64 + mt * 16 + (lane >> 2) + rh * 8;
            const int slot = m0 + r;
            if (slot < c) {
#pragma unroll
                for (int nt = 0; nt < 4; nt++) {
                    const int col = n0 + warp_n * 32 + nt * 8 + (lane & 3) * 2;
                    const float v0 = acc[mt][nt][rh * 2 + 0] + __ldg(&bias[col]);
                    const float v1 = acc[mt][nt][rh * 2 + 1] + __ldg(&bias[col + 1]);
                    if (PHASE == 1) {
                        __half2 hv = __floats2half2_rn(gelu_f(v0), gelu_f(v1));
                        *(__half2*)(g_h + ((size_t)e * TOKENS + slot) * DFF + col) = hv;
                    } else {
                        *(float2*)(g_y + ((size_t)e * TOKENS + slot) * DM + col) =
                            make_float2(v0, v1);
                    }
                }
            }
        }
    }
}

// ---------------- launch ----------------
extern "C" void kernel_launch(void* const* d_in, const int* in_sizes, int n_in,
                              void* d_out, int out_size) {
    const float* x  = (const float*)d_in[0];
    const float* Wg = (const float*)d_in[1];
    const float* bg = (const float*)d_in[2];
    const float* W1 = (const float*)d_in[3];
    const float* b1 = (const float*)d_in[4];
    const float* W2 = (const float*)d_in[5];
    const float* b2 = (const float*)d_in[6];
    float* out = (float*)d_out;

    cudaFuncSetAttribute(moe_gemm_kernel<1>,
                         cudaFuncAttributeMaxDynamicSharedMemorySize, SMEM_GEMM);
    cudaFuncSetAttribute(moe_gemm_kernel<2>,
                         cudaFuncAttributeMaxDynamicSharedMemorySize, SMEM_GEMM);

    zero_cnt_kernel<<<1, 32>>>();
    gate_kernel<<<TOKENS / 8, 256>>>(x, Wg, bg);
    convert_x_kernel<<<(TOKENS * DM / 8) / 256, 256>>>(x);

    dim3 g1(TOKENS / 128, NE, DFF / 128);   // m innermost, n outermost
    moe_gemm_kernel<1><<<g1, 256, SMEM_GEMM>>>(W1, b1);
    dim3 g2(TOKENS / 128, NE, DM / 128);
    moe_gemm_kernel<2><<<g2, 256, SMEM_GEMM>>>(W2, b2);

    combine_kernel<<<TOKENS, 256>>>(out);
}